// round 4
// baseline (speedup 1.0000x reference)
#include <cuda_runtime.h>

#define KN_MAXN 10000
#define KN_MAXE 100000

// Scratch (__device__ globals; zero-initialized at load)
__device__ int g_counts[KN_MAXN];
__device__ int g_offsets[KN_MAXN + 1];
__device__ int g_cursor[KN_MAXN];
__device__ int g_sorted[KN_MAXE];

__device__ __forceinline__ int zmap(int z) {
    // ZS = [1,6,7,8,9] -> 0..4
    return (z == 1) ? 0 : (z - 5);
}

__global__ void k_hist(const int* __restrict__ recv, int E) {
    int e = blockIdx.x * blockDim.x + threadIdx.x;
    if (e < E) atomicAdd(&g_counts[recv[e]], 1);
}

// Single-pass block scan + cursor init: 1024 threads, contiguous chunks.
__global__ void k_scan(int N) {
    __shared__ int warpsums[32];
    const int t = threadIdx.x;
    const int P = (N + 1023) >> 10;
    const int start = t * P;
    int s = 0;
    for (int k = 0; k < P; k++) {
        int i = start + k;
        if (i < N) s += g_counts[i];
    }
    int lane = t & 31, wid = t >> 5;
    int x = s;
#pragma unroll
    for (int off = 1; off < 32; off <<= 1) {
        int y = __shfl_up_sync(0xffffffffu, x, off);
        if (lane >= off) x += y;
    }
    if (lane == 31) warpsums[wid] = x;
    __syncthreads();
    if (wid == 0) {
        int w = warpsums[lane];
#pragma unroll
        for (int off = 1; off < 32; off <<= 1) {
            int y = __shfl_up_sync(0xffffffffu, w, off);
            if (lane >= off) w += y;
        }
        warpsums[lane] = w;
    }
    __syncthreads();
    int run = x - s + (wid > 0 ? warpsums[wid - 1] : 0);
    for (int k = 0; k < P; k++) {
        int i = start + k;
        if (i < N) {
            int v = g_counts[i];
            g_offsets[i] = run;
            g_cursor[i] = run;
            run += v;
        }
    }
    if (t == 1023) g_offsets[N] = run;
}

__global__ void k_scatter(const int* __restrict__ recv, int E) {
    int e = blockIdx.x * blockDim.x + threadIdx.x;
    if (e < E) {
        int p = atomicAdd(&g_cursor[recv[e]], 1);
        g_sorted[p] = e;
    }
}

// Fully fused per-node kernel. 80 threads = (l in 0..9, c2 in 0..7); each
// thread owns 2 enc columns -> acc[24]. Edge records built cooperatively in
// shared (rad->R contraction in-shared), never touching DRAM.
// Shared record layout per edge (stride 72 floats):
//   [0:36) R[lg][b], [36:46) ang, [48:64) enc, [64:72) rad
__global__ __launch_bounds__(80) void k_node(
    const int* __restrict__ an, const int* __restrict__ e_send,
    const float* __restrict__ dij, const float* __restrict__ uij,
    const float* __restrict__ Wsend, const float* __restrict__ Wrecv,
    const float* __restrict__ widths, const float* __restrict__ Wrad,
    float* __restrict__ out, int N)
{
    const int n = blockIdx.x;
    const int tid = threadIdx.x;

    __shared__ float  sBuf[2496];   // edge records (32 x 72) / output staging
    __shared__ float4 sW4[72];      // W_rad (3 x 8 x 12)
    __shared__ float  sWs[20];      // W_send
    __shared__ float  sEmbR[4];     // this node's recv embedding
    __shared__ float  sInv[8];      // 0.5/width^2

    if (tid < 72) sW4[tid] = ((const float4*)Wrad)[tid];
    if (tid < 20) sWs[tid] = Wsend[tid];
    if (tid >= 20 && tid < 28) { float w = widths[tid - 20]; sInv[tid - 20] = 0.5f / (w * w); }
    if (tid >= 28 && tid < 32) { int zi = zmap(an[n]); sEmbR[tid - 28] = Wrecv[zi * 4 + tid - 28]; }
    if (tid == 0) g_counts[n] = 0;   // reset histogram for next graph replay
    __syncthreads();

    const int lo = g_offsets[n];
    const int hi = g_offsets[n + 1];
    const int l = tid >> 3;
    const int c2 = tid & 7;
    const int lg3 = ((l == 0) ? 0 : ((l < 4) ? 1 : 2)) * 3;

    float acc[24];
#pragma unroll
    for (int b = 0; b < 24; b++) acc[b] = 0.f;

    for (int base = lo; base < hi; base += 32) {
        const int nb = min(32, hi - base);
        // Stage raw edge data: rad, ang, enc
        if (tid < nb) {
            float* rec = sBuf + tid * 72;
            int e = g_sorted[base + tid];
            float d = dij[e];
            float ux = uij[3 * e + 0], uy = uij[3 * e + 1], uz = uij[3 * e + 2];
            // cutoff p=5: 1 - 21 x^5 + 35 x^6 - 15 x^7
            float xr = d * 0.25f;
            float x2 = xr * xr;
            float x5 = x2 * x2 * xr;
            float env = 1.f - 21.f * x5 + 35.f * x5 * xr - 15.f * x5 * x2;
            float rc = (d < 4.f) ? env : 0.f;
            float d2 = d * d;
#pragma unroll
            for (int r = 0; r < 8; r++) rec[64 + r] = __expf(-d2 * sInv[r]) * rc;
            rec[36] = 1.f;
            rec[37] = ux; rec[38] = uy; rec[39] = uz;
            rec[40] = ux * ux; rec[41] = ux * uy; rec[42] = ux * uz;
            rec[43] = uy * uy; rec[44] = uy * uz; rec[45] = uz * uz;
            int zi = zmap(an[e_send[e]]);
#pragma unroll
            for (int i = 0; i < 4; i++) {
                float es = sWs[zi * 4 + i];
#pragma unroll
                for (int j = 0; j < 4; j++)
                    rec[48 + i * 4 + j] = es * sEmbR[j];
            }
        }
        __syncthreads();
        // Cooperative contraction: R[e][q] (q = float4 index 0..8) from rad
        for (int i = tid; i < nb * 9; i += 80) {
            int e = i / 9;
            int q = i - e * 9;
            int lg = q / 3;
            int bq = q - lg * 3;
            const float* radp = sBuf + e * 72 + 64;
            float4 o = make_float4(0.f, 0.f, 0.f, 0.f);
#pragma unroll
            for (int r = 0; r < 8; r++) {
                float a = radp[r];
                float4 w = sW4[lg * 24 + r * 3 + bq];
                o.x = fmaf(a, w.x, o.x); o.y = fmaf(a, w.y, o.y);
                o.z = fmaf(a, w.z, o.z); o.w = fmaf(a, w.w, o.w);
            }
            ((float4*)(sBuf + e * 72))[q] = o;
        }
        __syncthreads();
        // Accumulate: acc[b][0..1] += R[lg][b] * ang[l] * enc[c]
        const float* ep = sBuf;
        for (int j = 0; j < nb; j++, ep += 72) {
            float a = ep[36 + l];
            float2 en = *(const float2*)(ep + 48 + 2 * c2);
            float p0 = a * en.x, p1 = a * en.y;
            const float4* R4 = (const float4*)ep + lg3;
            float4 r0 = R4[0], r1 = R4[1], r2 = R4[2];
            acc[0]  = fmaf(r0.x, p0, acc[0]);  acc[12] = fmaf(r0.x, p1, acc[12]);
            acc[1]  = fmaf(r0.y, p0, acc[1]);  acc[13] = fmaf(r0.y, p1, acc[13]);
            acc[2]  = fmaf(r0.z, p0, acc[2]);  acc[14] = fmaf(r0.z, p1, acc[14]);
            acc[3]  = fmaf(r0.w, p0, acc[3]);  acc[15] = fmaf(r0.w, p1, acc[15]);
            acc[4]  = fmaf(r1.x, p0, acc[4]);  acc[16] = fmaf(r1.x, p1, acc[16]);
            acc[5]  = fmaf(r1.y, p0, acc[5]);  acc[17] = fmaf(r1.y, p1, acc[17]);
            acc[6]  = fmaf(r1.z, p0, acc[6]);  acc[18] = fmaf(r1.z, p1, acc[18]);
            acc[7]  = fmaf(r1.w, p0, acc[7]);  acc[19] = fmaf(r1.w, p1, acc[19]);
            acc[8]  = fmaf(r2.x, p0, acc[8]);  acc[20] = fmaf(r2.x, p1, acc[20]);
            acc[9]  = fmaf(r2.y, p0, acc[9]);  acc[21] = fmaf(r2.y, p1, acc[21]);
            acc[10] = fmaf(r2.z, p0, acc[10]); acc[22] = fmaf(r2.z, p1, acc[22]);
            acc[11] = fmaf(r2.w, p0, acc[11]); acc[23] = fmaf(r2.w, p1, acc[23]);
        }
        __syncthreads();   // before next batch overwrites sBuf
    }

    // Stage output in shared: [a0(192) | a1(576) | a2(1728)], write coalesced.
#pragma unroll
    for (int h = 0; h < 2; h++) {
        const int c = 2 * c2 + h;
        const float* v = acc + 12 * h;
        if (l == 0) {
#pragma unroll
            for (int b = 0; b < 12; b++) sBuf[b * 16 + c] = v[b];
        } else if (l < 4) {
            float* p = sBuf + 192 + (l - 1);
#pragma unroll
            for (int b = 0; b < 12; b++) p[(b * 16 + c) * 3] = v[b];
        } else {
            const int P1[6] = {0, 1, 2, 4, 5, 8};
            const int P2[6] = {-1, 3, 6, -1, 7, -1};
            int li = l - 4;
            int o1 = P1[li], o2 = P2[li];
            float* p = sBuf + 768;
#pragma unroll
            for (int b = 0; b < 12; b++) {
                float w = v[b];
                int k9 = (b * 16 + c) * 9;
                p[k9 + o1] = w;
                if (o2 >= 0) p[k9 + o2] = w;
            }
        }
    }
    __syncthreads();

    const float4* s4 = (const float4*)sBuf;
    float4* g0 = (float4*)(out + (size_t)n * 192);
    float4* g1 = (float4*)(out + (size_t)N * 192 + (size_t)n * 576);
    float4* g2 = (float4*)(out + (size_t)N * 768 + (size_t)n * 1728);
    for (int i = tid; i < 624; i += 80) {
        float4 v = s4[i];
        if (i < 48)       g0[i]       = v;
        else if (i < 192) g1[i - 48]  = v;
        else              g2[i - 192] = v;
    }
}

extern "C" void kernel_launch(void* const* d_in, const int* in_sizes, int n_in,
                              void* d_out, int out_size) {
    const int*   an     = (const int*)d_in[0];    // atomic_numbers (N)
    const int*   eidx   = (const int*)d_in[1];    // edge_index (2,E)
    const float* dij    = (const float*)d_in[2];  // (E)
    const float* uij    = (const float*)d_in[3];  // (E,3)
    // d_in[4] = positions (unused by reference math)
    const float* Wsend  = (const float*)d_in[5];  // (5,4)
    const float* Wrecv  = (const float*)d_in[6];  // (5,4)
    const float* widths = (const float*)d_in[7];  // (8)
    const float* Wrad   = (const float*)d_in[8];  // (3,8,12)
    float* out = (float*)d_out;

    int N = in_sizes[0];
    int E = in_sizes[2];
    const int* e_send = eidx;
    const int* e_recv = eidx + E;

    // g_counts: zero at load, re-zeroed each call by k_node.
    k_hist<<<(E + 255) / 256, 256>>>(e_recv, E);
    k_scan<<<1, 1024>>>(N);
    k_scatter<<<(E + 255) / 256, 256>>>(e_recv, E);
    k_node<<<N, 80>>>(an, e_send, dij, uij, Wsend, Wrecv, widths, Wrad, out, N);
}

// round 7
// speedup vs baseline: 1.0085x; 1.0085x over previous
#include <cuda_runtime.h>

#define KN_MAXN 10000
#define KN_MAXE 100000

// Scratch (__device__ globals; zero-initialized at load)
__device__ int g_counts[KN_MAXN];
__device__ int g_offsets[KN_MAXN + 1];
__device__ int g_cursor[KN_MAXN];
__device__ int g_sorted[KN_MAXE];

__device__ __forceinline__ int zmap(int z) {
    // ZS = [1,6,7,8,9] -> 0..4
    return (z == 1) ? 0 : (z - 5);
}

__global__ void k_hist(const int* __restrict__ recv, int E) {
    int e = blockIdx.x * blockDim.x + threadIdx.x;
    if (e < E) atomicAdd(&g_counts[recv[e]], 1);
}

// Single-pass block scan + cursor init: 1024 threads, contiguous chunks.
__global__ void k_scan(int N) {
    __shared__ int warpsums[32];
    const int t = threadIdx.x;
    const int P = (N + 1023) >> 10;
    const int start = t * P;
    int s = 0;
    for (int k = 0; k < P; k++) {
        int i = start + k;
        if (i < N) s += g_counts[i];
    }
    int lane = t & 31, wid = t >> 5;
    int x = s;
#pragma unroll
    for (int off = 1; off < 32; off <<= 1) {
        int y = __shfl_up_sync(0xffffffffu, x, off);
        if (lane >= off) x += y;
    }
    if (lane == 31) warpsums[wid] = x;
    __syncthreads();
    if (wid == 0) {
        int w = warpsums[lane];
#pragma unroll
        for (int off = 1; off < 32; off <<= 1) {
            int y = __shfl_up_sync(0xffffffffu, w, off);
            if (lane >= off) w += y;
        }
        warpsums[lane] = w;
    }
    __syncthreads();
    int run = x - s + (wid > 0 ? warpsums[wid - 1] : 0);
    for (int k = 0; k < P; k++) {
        int i = start + k;
        if (i < N) {
            int v = g_counts[i];
            g_offsets[i] = run;
            g_cursor[i] = run;
            run += v;
        }
    }
    if (t == 1023) g_offsets[N] = run;
}

__global__ void k_scatter(const int* __restrict__ recv, int E) {
    int e = blockIdx.x * blockDim.x + threadIdx.x;
    if (e < E) {
        int p = atomicAdd(&g_cursor[recv[e]], 1);
        g_sorted[p] = e;
    }
}

// Fused per-node kernel, 160 threads = (l in 0..9, c in 0..15).
// Per batch of <=32 edges:
//   Phase A (tid<nb): raw edge math -> shared record (stride 72):
//     [0:36) R (filled in B), [36:46) ang, [48:64) enc, [64:72) rad
//   Phase B (all): cooperative rad->R contraction (nb*9 float4 items)
//   Phase C (all): acc[12] += R[lg(l)][:] * ang[l] * enc[c]
__global__ __launch_bounds__(160) void k_node(
    const int* __restrict__ an, const int* __restrict__ e_send,
    const float* __restrict__ dij, const float* __restrict__ uij,
    const float* __restrict__ Wsend, const float* __restrict__ Wrecv,
    const float* __restrict__ widths, const float* __restrict__ Wrad,
    float* __restrict__ out, int N)
{
    const int n = blockIdx.x;
    const int tid = threadIdx.x;

    __shared__ float  sBuf[2496];   // edge records (32 x 72) / output staging
    __shared__ float4 sW4[72];      // W_rad (3 x 8 x 12)
    __shared__ float  sWs[20];      // W_send
    __shared__ float  sEmbR[4];     // this node's recv embedding
    __shared__ float  sInv[8];      // 0.5/width^2

    if (tid < 72) sW4[tid] = ((const float4*)Wrad)[tid];
    if (tid >= 80 && tid < 100) sWs[tid - 80] = Wsend[tid - 80];
    if (tid >= 100 && tid < 108) { float w = widths[tid - 100]; sInv[tid - 100] = 0.5f / (w * w); }
    if (tid >= 108 && tid < 112) { int zi = zmap(an[n]); sEmbR[tid - 108] = Wrecv[zi * 4 + tid - 108]; }
    if (tid == 112) g_counts[n] = 0;   // reset histogram for next graph replay
    __syncthreads();

    const int lo = g_offsets[n];
    const int hi = g_offsets[n + 1];
    const int l = tid >> 4;
    const int c = tid & 15;
    const int lg3 = ((l == 0) ? 0 : ((l < 4) ? 1 : 2)) * 3;

    float acc[12];
#pragma unroll
    for (int b = 0; b < 12; b++) acc[b] = 0.f;

    for (int base = lo; base < hi; base += 32) {
        const int nb = min(32, hi - base);
        // Phase A: raw edge math
        if (tid < nb) {
            float* rec = sBuf + tid * 72;
            int e = g_sorted[base + tid];
            float d = dij[e];
            float ux = uij[3 * e + 0], uy = uij[3 * e + 1], uz = uij[3 * e + 2];
            // cutoff p=5: 1 - 21 x^5 + 35 x^6 - 15 x^7
            float xr = d * 0.25f;
            float x2 = xr * xr;
            float x5 = x2 * x2 * xr;
            float env = 1.f - 21.f * x5 + 35.f * x5 * xr - 15.f * x5 * x2;
            float rc = (d < 4.f) ? env : 0.f;
            float d2 = d * d;
#pragma unroll
            for (int r = 0; r < 8; r++) rec[64 + r] = __expf(-d2 * sInv[r]) * rc;
            rec[36] = 1.f;
            rec[37] = ux; rec[38] = uy; rec[39] = uz;
            rec[40] = ux * ux; rec[41] = ux * uy; rec[42] = ux * uz;
            rec[43] = uy * uy; rec[44] = uy * uz; rec[45] = uz * uz;
            int zi = zmap(an[e_send[e]]);
#pragma unroll
            for (int i = 0; i < 4; i++) {
                float es = sWs[zi * 4 + i];
#pragma unroll
                for (int j = 0; j < 4; j++)
                    rec[48 + i * 4 + j] = es * sEmbR[j];
            }
        }
        __syncthreads();
        // Phase B: cooperative rad->R contraction
        for (int i = tid; i < nb * 9; i += 160) {
            int e = i / 9;
            int q = i - e * 9;
            int lg = q / 3;
            int bq = q - lg * 3;
            const float* radp = sBuf + e * 72 + 64;
            float4 o = make_float4(0.f, 0.f, 0.f, 0.f);
#pragma unroll
            for (int r = 0; r < 8; r++) {
                float a = radp[r];
                float4 w = sW4[lg * 24 + r * 3 + bq];
                o.x = fmaf(a, w.x, o.x); o.y = fmaf(a, w.y, o.y);
                o.z = fmaf(a, w.z, o.z); o.w = fmaf(a, w.w, o.w);
            }
            ((float4*)(sBuf + e * 72))[q] = o;
        }
        __syncthreads();
        // Phase C: accumulate
        const float* ep = sBuf;
        for (int j = 0; j < nb; j++, ep += 72) {
            float p = ep[36 + l] * ep[48 + c];
            const float4* R4 = (const float4*)ep + lg3;
            float4 r0 = R4[0], r1 = R4[1], r2 = R4[2];
            acc[0]  = fmaf(r0.x, p, acc[0]);  acc[1]  = fmaf(r0.y, p, acc[1]);
            acc[2]  = fmaf(r0.z, p, acc[2]);  acc[3]  = fmaf(r0.w, p, acc[3]);
            acc[4]  = fmaf(r1.x, p, acc[4]);  acc[5]  = fmaf(r1.y, p, acc[5]);
            acc[6]  = fmaf(r1.z, p, acc[6]);  acc[7]  = fmaf(r1.w, p, acc[7]);
            acc[8]  = fmaf(r2.x, p, acc[8]);  acc[9]  = fmaf(r2.y, p, acc[9]);
            acc[10] = fmaf(r2.z, p, acc[10]); acc[11] = fmaf(r2.w, p, acc[11]);
        }
        __syncthreads();   // before next batch overwrites sBuf
    }

    // Stage output in shared: [a0(192) | a1(576) | a2(1728)], write coalesced.
    if (l == 0) {
#pragma unroll
        for (int b = 0; b < 12; b++) sBuf[b * 16 + c] = acc[b];
    } else if (l < 4) {
        float* p = sBuf + 192 + (l - 1);
#pragma unroll
        for (int b = 0; b < 12; b++) p[(b * 16 + c) * 3] = acc[b];
    } else {
        const int P1[6] = {0, 1, 2, 4, 5, 8};
        const int P2[6] = {-1, 3, 6, -1, 7, -1};
        int li = l - 4;
        int o1 = P1[li], o2 = P2[li];
        float* p = sBuf + 768;
#pragma unroll
        for (int b = 0; b < 12; b++) {
            float v = acc[b];
            int k9 = (b * 16 + c) * 9;
            p[k9 + o1] = v;
            if (o2 >= 0) p[k9 + o2] = v;
        }
    }
    __syncthreads();

    const float4* s4 = (const float4*)sBuf;
    float4* g0 = (float4*)(out + (size_t)n * 192);
    float4* g1 = (float4*)(out + (size_t)N * 192 + (size_t)n * 576);
    float4* g2 = (float4*)(out + (size_t)N * 768 + (size_t)n * 1728);
    for (int i = tid; i < 624; i += 160) {
        float4 v = s4[i];
        if (i < 48)       g0[i]       = v;
        else if (i < 192) g1[i - 48]  = v;
        else              g2[i - 192] = v;
    }
}

extern "C" void kernel_launch(void* const* d_in, const int* in_sizes, int n_in,
                              void* d_out, int out_size) {
    const int*   an     = (const int*)d_in[0];    // atomic_numbers (N)
    const int*   eidx   = (const int*)d_in[1];    // edge_index (2,E)
    const float* dij    = (const float*)d_in[2];  // (E)
    const float* uij    = (const float*)d_in[3];  // (E,3)
    // d_in[4] = positions (unused by reference math)
    const float* Wsend  = (const float*)d_in[5];  // (5,4)
    const float* Wrecv  = (const float*)d_in[6];  // (5,4)
    const float* widths = (const float*)d_in[7];  // (8)
    const float* Wrad   = (const float*)d_in[8];  // (3,8,12)
    float* out = (float*)d_out;

    int N = in_sizes[0];
    int E = in_sizes[2];
    const int* e_send = eidx;
    const int* e_recv = eidx + E;

    // g_counts: zero at load, re-zeroed each call by k_node.
    k_hist<<<(E + 255) / 256, 256>>>(e_recv, E);
    k_scan<<<1, 1024>>>(N);
    k_scatter<<<(E + 255) / 256, 256>>>(e_recv, E);
    k_node<<<N, 160>>>(an, e_send, dij, uij, Wsend, Wrecv, widths, Wrad, out, N);
}

// round 8
// speedup vs baseline: 1.1826x; 1.1727x over previous
#include <cuda_runtime.h>

#define KN_MAXN 10000
#define KN_MAXE 100000

// Scratch (__device__ globals; zero-initialized at load)
__device__ int g_counts[KN_MAXN];
__device__ int g_offsets[KN_MAXN + 1];
__device__ int g_cursor[KN_MAXN];
__device__ int g_sorted[KN_MAXE];

__device__ __forceinline__ int zmap(int z) {
    // ZS = [1,6,7,8,9] -> 0..4
    return (z == 1) ? 0 : (z - 5);
}

__global__ void k_hist(const int* __restrict__ recv, int E) {
    int e = blockIdx.x * blockDim.x + threadIdx.x;
    if (e < E) atomicAdd(&g_counts[recv[e]], 1);
}

// Single-pass block scan + cursor init: 1024 threads, contiguous chunks.
__global__ void k_scan(int N) {
    __shared__ int warpsums[32];
    const int t = threadIdx.x;
    const int P = (N + 1023) >> 10;
    const int start = t * P;
    int s = 0;
    for (int k = 0; k < P; k++) {
        int i = start + k;
        if (i < N) s += g_counts[i];
    }
    int lane = t & 31, wid = t >> 5;
    int x = s;
#pragma unroll
    for (int off = 1; off < 32; off <<= 1) {
        int y = __shfl_up_sync(0xffffffffu, x, off);
        if (lane >= off) x += y;
    }
    if (lane == 31) warpsums[wid] = x;
    __syncthreads();
    if (wid == 0) {
        int w = warpsums[lane];
#pragma unroll
        for (int off = 1; off < 32; off <<= 1) {
            int y = __shfl_up_sync(0xffffffffu, w, off);
            if (lane >= off) w += y;
        }
        warpsums[lane] = w;
    }
    __syncthreads();
    int run = x - s + (wid > 0 ? warpsums[wid - 1] : 0);
    for (int k = 0; k < P; k++) {
        int i = start + k;
        if (i < N) {
            int v = g_counts[i];
            g_offsets[i] = run;
            g_cursor[i] = run;
            run += v;
        }
    }
    if (t == 1023) g_offsets[N] = run;
}

__global__ void k_scatter(const int* __restrict__ recv, int E) {
    int e = blockIdx.x * blockDim.x + threadIdx.x;
    if (e < E) {
        int p = atomicAdd(&g_cursor[recv[e]], 1);
        g_sorted[p] = e;
    }
}

// Per-node kernel with receiver-embedding factorization.
// 160 threads: tid = l*16 + i*4 + rh  (l in 0..9, i in 0..3, rh in 0..3).
// Edge loop accumulates S[l,i,r] (2 radials per thread, factor embR removed).
// Epilogue: S --W_rad--> B[l,i,b] once per node, feat = B * embR[j], staged
// in shared and written coalesced.
__global__ __launch_bounds__(160) void k_node(
    const int* __restrict__ an, const int* __restrict__ e_send,
    const float* __restrict__ dij, const float* __restrict__ uij,
    const float* __restrict__ Wsend, const float* __restrict__ Wrecv,
    const float* __restrict__ widths, const float* __restrict__ Wrad,
    float* __restrict__ out, int N)
{
    const int n = blockIdx.x;
    const int tid = threadIdx.x;

    __shared__ float  sBuf[2496];   // edge arrays (ang|embS|rad2) then output staging
    __shared__ float  sS[320];      // S[l*4+i][r]
    __shared__ float4 sB4[120];     // B[l*4+i][b] as 3 float4 per li
    __shared__ float4 sW4[72];      // W_rad (3 x 8 x 12)
    __shared__ float  sWs[20];      // W_send
    __shared__ float  sEmbR[4];     // this node's recv embedding
    __shared__ float  sInv[8];      // 0.5/width^2

    if (tid < 72) sW4[tid] = ((const float4*)Wrad)[tid];
    if (tid >= 80 && tid < 100) sWs[tid - 80] = Wsend[tid - 80];
    if (tid >= 100 && tid < 108) { float w = widths[tid - 100]; sInv[tid - 100] = 0.5f / (w * w); }
    if (tid >= 108 && tid < 112) { int zi = zmap(an[n]); sEmbR[tid - 108] = Wrecv[zi * 4 + tid - 108]; }
    if (tid == 112) g_counts[n] = 0;   // reset histogram for next graph replay
    __syncthreads();

    const int lo = g_offsets[n];
    const int hi = g_offsets[n + 1];
    const int l  = tid >> 4;
    const int i4 = (tid >> 2) & 3;
    const int rh = tid & 3;
    const int li = tid >> 2;           // l*4 + i

    // Edge-array views inside sBuf:
    //   ang  : sBuf[0   + e*10 + l]
    //   embS : sBuf[320 + e*4  + i]
    //   rad2 : ((float2*)(sBuf+448))[e*4 + rh]
    float accx = 0.f, accy = 0.f;

    for (int base = lo; base < hi; base += 32) {
        const int nb = min(32, hi - base);
        // Phase A: raw edge math (rad, ang, embS)
        if (tid < nb) {
            int e = g_sorted[base + tid];
            float d = dij[e];
            float ux = uij[3 * e + 0], uy = uij[3 * e + 1], uz = uij[3 * e + 2];
            // cutoff p=5: 1 - 21 x^5 + 35 x^6 - 15 x^7
            float xr = d * 0.25f;
            float x2 = xr * xr;
            float x5 = x2 * x2 * xr;
            float env = 1.f - 21.f * x5 + 35.f * x5 * xr - 15.f * x5 * x2;
            float rc = (d < 4.f) ? env : 0.f;
            float d2 = d * d;
            float rv[8];
#pragma unroll
            for (int r = 0; r < 8; r++) rv[r] = __expf(-d2 * sInv[r]) * rc;
            float2* radp = (float2*)(sBuf + 448) + tid * 4;
            radp[0] = make_float2(rv[0], rv[1]);
            radp[1] = make_float2(rv[2], rv[3]);
            radp[2] = make_float2(rv[4], rv[5]);
            radp[3] = make_float2(rv[6], rv[7]);
            float* angp = sBuf + tid * 10;
            angp[0] = 1.f;
            angp[1] = ux; angp[2] = uy; angp[3] = uz;
            angp[4] = ux * ux; angp[5] = ux * uy; angp[6] = ux * uz;
            angp[7] = uy * uy; angp[8] = uy * uz; angp[9] = uz * uz;
            int zi = zmap(an[e_send[e]]);
            float* ep = sBuf + 320 + tid * 4;
            ep[0] = sWs[zi * 4 + 0];
            ep[1] = sWs[zi * 4 + 1];
            ep[2] = sWs[zi * 4 + 2];
            ep[3] = sWs[zi * 4 + 3];
        }
        __syncthreads();
        // Phase C: accumulate S (3 LDS + 3 flops per edge per thread)
        const float*  pAng = sBuf + l;
        const float*  pEmb = sBuf + 320 + i4;
        const float2* pRad = (const float2*)(sBuf + 448) + rh;
        for (int j = 0; j < nb; j++) {
            float p = pAng[j * 10] * pEmb[j * 4];
            float2 r2 = pRad[j * 4];
            accx = fmaf(r2.x, p, accx);
            accy = fmaf(r2.y, p, accy);
        }
        __syncthreads();   // before next batch overwrites sBuf
    }

    // Publish S
    ((float2*)sS)[li * 4 + rh] = make_float2(accx, accy);
    __syncthreads();

    // B contraction: 120 work items (li in 0..39, bq in 0..2)
    if (tid < 120) {
        int wli = tid / 3;
        int bq = tid - wli * 3;
        int wl = wli >> 2;
        int lg = (wl == 0) ? 0 : ((wl < 4) ? 1 : 2);
        const float* Sp = sS + wli * 8;
        const float4* Wp = sW4 + lg * 24 + bq;
        float4 o = make_float4(0.f, 0.f, 0.f, 0.f);
#pragma unroll
        for (int r = 0; r < 8; r++) {
            float a = Sp[r];
            float4 w = Wp[r * 3];
            o.x = fmaf(a, w.x, o.x); o.y = fmaf(a, w.y, o.y);
            o.z = fmaf(a, w.z, o.z); o.w = fmaf(a, w.w, o.w);
        }
        sB4[wli * 3 + bq] = o;
    }
    __syncthreads();

    // Stage output: thread = (l, c) with c = i*4+j; val[b] = B[li][b]*embR[j]
    const int c = tid & 15;
    const float er = sEmbR[c & 3];
    const int sli = l * 4 + (c >> 2);
    float val[12];
#pragma unroll
    for (int bq = 0; bq < 3; bq++) {
        float4 v = sB4[sli * 3 + bq];
        val[bq * 4 + 0] = v.x * er;
        val[bq * 4 + 1] = v.y * er;
        val[bq * 4 + 2] = v.z * er;
        val[bq * 4 + 3] = v.w * er;
    }

    // sOut = [a0(192) | a1(576) | a2(1728)] in sBuf (edge arrays dead now)
    if (l == 0) {
#pragma unroll
        for (int b = 0; b < 12; b++) sBuf[b * 16 + c] = val[b];
    } else if (l < 4) {
        float* p = sBuf + 192 + (l - 1);
#pragma unroll
        for (int b = 0; b < 12; b++) p[(b * 16 + c) * 3] = val[b];
    } else {
        const int P1[6] = {0, 1, 2, 4, 5, 8};
        const int P2[6] = {-1, 3, 6, -1, 7, -1};
        int lix = l - 4;
        int o1 = P1[lix], o2 = P2[lix];
        float* p = sBuf + 768;
#pragma unroll
        for (int b = 0; b < 12; b++) {
            float v = val[b];
            int k9 = (b * 16 + c) * 9;
            p[k9 + o1] = v;
            if (o2 >= 0) p[k9 + o2] = v;
        }
    }
    __syncthreads();

    const float4* s4 = (const float4*)sBuf;
    float4* g0 = (float4*)(out + (size_t)n * 192);
    float4* g1 = (float4*)(out + (size_t)N * 192 + (size_t)n * 576);
    float4* g2 = (float4*)(out + (size_t)N * 768 + (size_t)n * 1728);
    for (int q = tid; q < 624; q += 160) {
        float4 v = s4[q];
        if (q < 48)       g0[q]       = v;
        else if (q < 192) g1[q - 48]  = v;
        else              g2[q - 192] = v;
    }
}

extern "C" void kernel_launch(void* const* d_in, const int* in_sizes, int n_in,
                              void* d_out, int out_size) {
    const int*   an     = (const int*)d_in[0];    // atomic_numbers (N)
    const int*   eidx   = (const int*)d_in[1];    // edge_index (2,E)
    const float* dij    = (const float*)d_in[2];  // (E)
    const float* uij    = (const float*)d_in[3];  // (E,3)
    // d_in[4] = positions (unused by reference math)
    const float* Wsend  = (const float*)d_in[5];  // (5,4)
    const float* Wrecv  = (const float*)d_in[6];  // (5,4)
    const float* widths = (const float*)d_in[7];  // (8)
    const float* Wrad   = (const float*)d_in[8];  // (3,8,12)
    float* out = (float*)d_out;

    int N = in_sizes[0];
    int E = in_sizes[2];
    const int* e_send = eidx;
    const int* e_recv = eidx + E;

    // g_counts: zero at load, re-zeroed each call by k_node.
    k_hist<<<(E + 255) / 256, 256>>>(e_recv, E);
    k_scan<<<1, 1024>>>(N);
    k_scatter<<<(E + 255) / 256, 256>>>(e_recv, E);
    k_node<<<N, 160>>>(an, e_send, dij, uij, Wsend, Wrecv, widths, Wrad, out, N);
}